// round 4
// baseline (speedup 1.0000x reference)
#include <cuda_runtime.h>
#include <cstdint>

// Problem constants (fixed by the dataset)
#define NMAX 100000
#define EMAX 1600000
#define HID  64

// ---------------- device scratch (no allocations allowed) ----------------
__device__ int   g_cnt[NMAX];
__device__ float g_dinv[NMAX];
__device__ int   g_rowptr[NMAX + 1];
__device__ int   g_woff[NMAX];
__device__ int   g_bsum[512];
__device__ int   g_boff[512];
__device__ int   g_csr_src[EMAX + NMAX];
__device__ float g_csr_w[EMAX + NMAX];
__device__ float g_H [(size_t)NMAX * HID];
__device__ float g_Xa[(size_t)NMAX * HID];
__device__ float g_Xb[(size_t)NMAX * HID];

// ---------------- graph build ----------------
__global__ void k_init_cnt(int n) {
    int i = blockIdx.x * blockDim.x + threadIdx.x;
    if (i < n) g_cnt[i] = 1;   // self-loop
}

__global__ void k_count(const int* __restrict__ dst, int e) {
    int i = blockIdx.x * blockDim.x + threadIdx.x;
    if (i < e) atomicAdd(&g_cnt[dst[i]], 1);
}

__global__ void k_blocksum(int n) {
    __shared__ int sh[256];
    int i = blockIdx.x * 256 + threadIdx.x;
    sh[threadIdx.x] = (i < n) ? g_cnt[i] : 0;
    __syncthreads();
    for (int off = 128; off; off >>= 1) {
        if (threadIdx.x < off) sh[threadIdx.x] += sh[threadIdx.x + off];
        __syncthreads();
    }
    if (threadIdx.x == 0) g_bsum[blockIdx.x] = sh[0];
}

// single block, 512 threads: exclusive scan of block sums
__global__ void k_topscan(int nblk) {
    __shared__ int sh[512];
    int t = threadIdx.x;
    int v = (t < nblk) ? g_bsum[t] : 0;
    sh[t] = v;
    for (int off = 1; off < 512; off <<= 1) {
        __syncthreads();
        int x = (t >= off) ? sh[t - off] : 0;
        __syncthreads();
        sh[t] += x;
    }
    __syncthreads();
    if (t < nblk) g_boff[t] = sh[t] - v;   // exclusive
}

__global__ void k_scanwrite(int n) {
    __shared__ int sh[256];
    int t = threadIdx.x;
    int i = blockIdx.x * 256 + t;
    int v = (i < n) ? g_cnt[i] : 0;
    sh[t] = v;
    for (int off = 1; off < 256; off <<= 1) {
        __syncthreads();
        int x = (t >= off) ? sh[t - off] : 0;
        __syncthreads();
        sh[t] += x;
    }
    __syncthreads();
    int excl = sh[t] - v;
    if (i < n) {
        int rp = g_boff[blockIdx.x] + excl;
        g_rowptr[i] = rp;
        float di = rsqrtf((float)v);
        g_dinv[i] = di;
        // self-loop edge first (deterministic slot)
        g_csr_src[rp] = i;
        g_csr_w[rp]   = di * di;
        g_woff[i] = rp + 1;
        if (i == n - 1) g_rowptr[n] = rp + v;
    }
}

__global__ void k_scatter(const int* __restrict__ src, const int* __restrict__ dst, int e) {
    int i = blockIdx.x * blockDim.x + threadIdx.x;
    if (i >= e) return;
    int s = src[i], d = dst[i];
    float w = g_dinv[s] * g_dinv[d];
    int pos = atomicAdd(&g_woff[d], 1);
    g_csr_src[pos] = s;
    g_csr_w[pos]   = w;
}

// ---------------- dense GEMM: C[n,64] = A[n,K] @ W[K,64] ----------------
template <int K>
__global__ void __launch_bounds__(256) k_gemm(const float* __restrict__ A,
                                              const float* __restrict__ W,
                                              float* __restrict__ Cc, int n) {
    constexpr int BM = 128, BN = 64, BK = 16;
    __shared__ float As[BK][BM];
    __shared__ float Ws[BK][BN];
    int tid = threadIdx.x;
    int m0 = blockIdx.x * BM;
    int tx = tid & 15;   // col group: cols tx*4 .. tx*4+3
    int ty = tid >> 4;   // row group: rows ty*8 .. ty*8+7
    float acc[8][4] = {};

    for (int k0 = 0; k0 < K; k0 += BK) {
        // A tile: 128x16 -> 512 float4, 2 per thread, stored transposed
        #pragma unroll
        for (int r = 0; r < 2; ++r) {
            int q = tid + r * 256;
            int row = q >> 2;
            int c4 = (q & 3) * 4;
            int gr = m0 + row;
            float4 v = make_float4(0.f, 0.f, 0.f, 0.f);
            if (gr < n) v = *reinterpret_cast<const float4*>(&A[(size_t)gr * K + k0 + c4]);
            As[c4 + 0][row] = v.x;
            As[c4 + 1][row] = v.y;
            As[c4 + 2][row] = v.z;
            As[c4 + 3][row] = v.w;
        }
        // W tile: 16x64 -> 256 float4, 1 per thread
        {
            int row = tid >> 4;
            int c4 = (tid & 15) * 4;
            float4 v = *reinterpret_cast<const float4*>(&W[(size_t)(k0 + row) * BN + c4]);
            *reinterpret_cast<float4*>(&Ws[row][c4]) = v;
        }
        __syncthreads();
        #pragma unroll
        for (int kk = 0; kk < BK; ++kk) {
            float4 a0 = *reinterpret_cast<const float4*>(&As[kk][ty * 8]);
            float4 a1 = *reinterpret_cast<const float4*>(&As[kk][ty * 8 + 4]);
            float4 wv = *reinterpret_cast<const float4*>(&Ws[kk][tx * 4]);
            float a[8] = {a0.x, a0.y, a0.z, a0.w, a1.x, a1.y, a1.z, a1.w};
            float wr[4] = {wv.x, wv.y, wv.z, wv.w};
            #pragma unroll
            for (int i = 0; i < 8; ++i)
                #pragma unroll
                for (int j = 0; j < 4; ++j)
                    acc[i][j] += a[i] * wr[j];
        }
        __syncthreads();
    }
    #pragma unroll
    for (int i = 0; i < 8; ++i) {
        int gr = m0 + ty * 8 + i;
        if (gr < n) {
            float4 v = make_float4(acc[i][0], acc[i][1], acc[i][2], acc[i][3]);
            *reinterpret_cast<float4*>(&Cc[(size_t)gr * 64 + tx * 4]) = v;
        }
    }
}

// ---------------- aggregation + bias + ELU: one warp per node ----------------
__global__ void __launch_bounds__(256) k_agg(const float* __restrict__ h,
                                             const float* __restrict__ bias,
                                             float* __restrict__ out, int n) {
    int node = (blockIdx.x * blockDim.x + threadIdx.x) >> 5;
    int lane = threadIdx.x & 31;
    if (node >= n) return;
    int start = g_rowptr[node];
    int end   = g_rowptr[node + 1];
    float acc0 = 0.f, acc1 = 0.f;
    int j = start;
    for (; j + 2 <= end; j += 2) {
        int s0 = g_csr_src[j];
        int s1 = g_csr_src[j + 1];
        float w0 = g_csr_w[j];
        float w1 = g_csr_w[j + 1];
        const float* p0 = h + (size_t)s0 * 64;
        const float* p1 = h + (size_t)s1 * 64;
        acc0 += w0 * p0[lane];
        acc1 += w0 * p0[lane + 32];
        acc0 += w1 * p1[lane];
        acc1 += w1 * p1[lane + 32];
    }
    if (j < end) {
        int s = g_csr_src[j];
        float w = g_csr_w[j];
        const float* p = h + (size_t)s * 64;
        acc0 += w * p[lane];
        acc1 += w * p[lane + 32];
    }
    acc0 += bias[lane];
    acc1 += bias[lane + 32];
    acc0 = acc0 > 0.f ? acc0 : expm1f(acc0);
    acc1 = acc1 > 0.f ? acc1 : expm1f(acc1);
    out[(size_t)node * 64 + lane]      = acc0;
    out[(size_t)node * 64 + lane + 32] = acc1;
}

// ---------------- final classifier: out[n,4] = [Xa|Xb] @ Wfc + bfc ----------------
__global__ void __launch_bounds__(256) k_final(const float* __restrict__ Wfc,
                                               const float* __restrict__ bfc,
                                               float* __restrict__ out, int n) {
    __shared__ float ws[128 * 4];
    for (int i = threadIdx.x; i < 512; i += 256) ws[i] = Wfc[i];
    __syncthreads();
    int node = (blockIdx.x * blockDim.x + threadIdx.x) >> 5;
    int lane = threadIdx.x & 31;
    if (node >= n) return;
    float v0 = g_Xa[(size_t)node * 64 + lane];
    float v1 = g_Xa[(size_t)node * 64 + lane + 32];
    float v2 = g_Xb[(size_t)node * 64 + lane];
    float v3 = g_Xb[(size_t)node * 64 + lane + 32];
    #pragma unroll
    for (int c = 0; c < 4; ++c) {
        float p = v0 * ws[lane * 4 + c]
                + v1 * ws[(lane + 32) * 4 + c]
                + v2 * ws[(64 + lane) * 4 + c]
                + v3 * ws[(96 + lane) * 4 + c];
        #pragma unroll
        for (int off = 16; off; off >>= 1)
            p += __shfl_xor_sync(0xffffffff, p, off);
        if (lane == 0) out[(size_t)node * 4 + c] = p + bfc[c];
    }
}

// ---------------- host launch ----------------
extern "C" void kernel_launch(void* const* d_in, const int* in_sizes, int n_in,
                              void* d_out, int out_size) {
    const float* x1  = (const float*)d_in[0];
    const float* x2  = (const float*)d_in[1];
    const int*   ei  = (const int*)d_in[2];
    const float* W1a = (const float*)d_in[3];
    const float* b1a = (const float*)d_in[4];
    const float* W2a = (const float*)d_in[5];
    const float* b2a = (const float*)d_in[6];
    const float* W1b = (const float*)d_in[7];
    const float* b1b = (const float*)d_in[8];
    const float* W2b = (const float*)d_in[9];
    const float* b2b = (const float*)d_in[10];
    const float* Wfc = (const float*)d_in[11];
    const float* bfc = (const float*)d_in[12];
    float* out = (float*)d_out;

    int n = in_sizes[0] / 512;   // 100000
    int e = in_sizes[2] / 2;     // 1600000
    const int* srcA = ei;
    const int* dstA = ei + e;

    float *pH, *pXa, *pXb;
    cudaGetSymbolAddress((void**)&pH,  g_H);
    cudaGetSymbolAddress((void**)&pXa, g_Xa);
    cudaGetSymbolAddress((void**)&pXb, g_Xb);

    int nblk = (n + 255) / 256;

    // graph build
    k_init_cnt<<<(n + 255) / 256, 256>>>(n);
    k_count<<<(e + 255) / 256, 256>>>(dstA, e);
    k_blocksum<<<nblk, 256>>>(n);
    k_topscan<<<1, 512>>>(nblk);
    k_scanwrite<<<nblk, 256>>>(n);
    k_scatter<<<(e + 255) / 256, 256>>>(srcA, dstA, e);

    int gemm_grid = (n + 127) / 128;
    int node_grid = (n * 32 + 255) / 256;   // one warp per node

    // branch 1
    k_gemm<512><<<gemm_grid, 256>>>(x1, W1a, pH, n);
    k_agg<<<node_grid, 256>>>(pH, b1a, pXa, n);
    k_gemm<64><<<gemm_grid, 256>>>(pXa, W2a, pH, n);
    k_agg<<<node_grid, 256>>>(pH, b2a, pXa, n);

    // branch 2
    k_gemm<256><<<gemm_grid, 256>>>(x2, W1b, pH, n);
    k_agg<<<node_grid, 256>>>(pH, b1b, pXb, n);
    k_gemm<64><<<gemm_grid, 256>>>(pXb, W2b, pH, n);
    k_agg<<<node_grid, 256>>>(pH, b2b, pXb, n);

    // classifier
    k_final<<<node_grid, 256>>>(Wfc, bfc, out, n);
}